// round 11
// baseline (speedup 1.0000x reference)
#include <cuda_runtime.h>
#include <cuda_bf16.h>
#include <stdint.h>
#include <math.h>

#define BB 16
#define NN 1024
#define FIN 256
#define FOUT 256
#define HH 8
#define ALPHA 0.2f

// Scratch (device globals; no allocations allowed)
__device__ float g_Wh[(size_t)BB * HH * NN * FOUT];
__device__ __nv_bfloat16 g_Whb[(size_t)BB * HH * NN * FOUT];
__device__ float g_ei[BB * HH * NN];
__device__ float g_ejb[BB * HH * NN];
__device__ __nv_bfloat16 g_hb[(size_t)8 * 16384 * 32];
__device__ __nv_bfloat16 g_hs[(size_t)8 * 16384 * 32];
__device__ __nv_bfloat16 g_wb[(size_t)8 * 2048 * 32];
__device__ __nv_bfloat16 g_ws[(size_t)8 * 2048 * 32];

#define MMA_BF16(c, a0, a1, a2, a3, b0, b1) \
    asm volatile("mma.sync.aligned.m16n8k16.row.col.f32.bf16.bf16.f32 " \
        "{%0,%1,%2,%3}, {%4,%5,%6,%7}, {%8,%9}, {%0,%1,%2,%3};" \
        : "+f"((c)[0]), "+f"((c)[1]), "+f"((c)[2]), "+f"((c)[3]) \
        : "r"(a0), "r"(a1), "r"(a2), "r"(a3), "r"(b0), "r"(b1))

#define PACK_BF16X2(r, lo, hi) \
    asm("cvt.rn.bf16x2.f32 %0, %1, %2;" : "=r"(r) : "f"(hi), "f"(lo))

#define CP16(dst, src) \
    asm volatile("cp.async.cg.shared.global [%0], [%1], 16;" :: "r"(dst), "l"(src) : "memory")
#define CP_COMMIT() asm volatile("cp.async.commit_group;" ::: "memory")
#define CP_WAIT1()  asm volatile("cp.async.wait_group 1;" ::: "memory")
#define CP_WAIT0()  asm volatile("cp.async.wait_group 0;" ::: "memory")

__device__ __forceinline__ uint32_t smem_u32(const void* p) {
    uint32_t a;
    asm("{ .reg .u64 t; cvta.to.shared.u64 t, %1; cvt.u32.u64 %0, t; }"
        : "=r"(a) : "l"(p));
    return a;
}
__device__ __forceinline__ void ldsm_x4(uint32_t& r0, uint32_t& r1,
                                        uint32_t& r2, uint32_t& r3, uint32_t addr) {
    asm volatile("ldmatrix.sync.aligned.m8n8.x4.shared.b16 {%0,%1,%2,%3}, [%4];"
                 : "=r"(r0), "=r"(r1), "=r"(r2), "=r"(r3) : "r"(addr));
}

// ---------------------------------------------------------------------------
// Prep: split fp32 -> big/small bf16, k-tiled [kt][row][32]
// ---------------------------------------------------------------------------
__global__ void split_h_kernel(const float* __restrict__ src)
{
    const int m = blockIdx.x;
    const int k = threadIdx.x;
    float x = src[(size_t)m * 256 + k];
    __nv_bfloat16 b = __float2bfloat16(x);
    __nv_bfloat16 s = __float2bfloat16(x - __bfloat162float(b));
    size_t idx = ((size_t)(k >> 5) * 16384 + m) * 32 + (k & 31);
    g_hb[idx] = b;
    g_hs[idx] = s;
}
__global__ void split_w_kernel(const float* __restrict__ src)
{
    const int j = blockIdx.x;
    const int k = threadIdx.x;
    float x = src[(size_t)j * 256 + k];
    __nv_bfloat16 b = __float2bfloat16(x);
    __nv_bfloat16 s = __float2bfloat16(x - __bfloat162float(b));
    size_t idx = ((size_t)(k >> 5) * 2048 + j) * 32 + (k & 31);
    g_wb[idx] = b;
    g_ws[idx] = s;
}

// ---------------------------------------------------------------------------
// Kernel 1: Wh = h @ W^T + bW via 3xBF16 m16n8k16 + cp.async (unchanged R8)
// ---------------------------------------------------------------------------
#define G1_PLANE_B 8192
#define G1_BUF (4 * G1_PLANE_B)
#define G1_SMEM (3 * G1_BUF)

__global__ void __launch_bounds__(256, 2) gemm1_cp_kernel(const float* __restrict__ bWp)
{
    extern __shared__ char gsm[];
    const uint32_t sbuf = smem_u32(gsm);

    const int tid  = threadIdx.x;
    const int lane = tid & 31;
    const int wid  = tid >> 5;
    const int mw   = wid & 1;
    const int nw   = wid >> 1;
    const int tg   = lane & 3;
    const int g    = lane >> 2;
    const int m0   = blockIdx.x * 128;
    const int j0   = blockIdx.y * 128;

    const int lrow = tid & 127;
    const int kh   = tid >> 7;
    const int swzr = (lrow & 3) ^ ((lrow >> 2) & 3);
    const uint32_t d0 = (uint32_t)lrow * 64 + (((2 * kh)     ^ swzr) << 4);
    const uint32_t d1 = (uint32_t)lrow * 64 + (((2 * kh + 1) ^ swzr) << 4);
    const char* srcAb = (const char*)g_hb + ((size_t)(m0 + lrow)) * 64 + kh * 32;
    const char* srcAs = (const char*)g_hs + ((size_t)(m0 + lrow)) * 64 + kh * 32;
    const char* srcBb = (const char*)g_wb + ((size_t)(j0 + lrow)) * 64 + kh * 32;
    const char* srcBs = (const char*)g_ws + ((size_t)(j0 + lrow)) * 64 + kh * 32;

    const int lro  = (lane & 7) + ((lane >> 3) & 1) * 8;
    const int lkc  = lane >> 4;
    const int swzL = (lro & 3) ^ ((lro >> 2) & 3);

    float acc[4][4][4];
#pragma unroll
    for (int mi = 0; mi < 4; mi++)
#pragma unroll
        for (int f = 0; f < 4; f++)
#pragma unroll
            for (int c = 0; c < 4; c++) acc[mi][f][c] = 0.f;

    {
        const uint32_t bb = sbuf;
        CP16(bb + d0, srcAb); CP16(bb + d1, srcAb + 16);
        CP16(bb + G1_PLANE_B + d0, srcAs); CP16(bb + G1_PLANE_B + d1, srcAs + 16);
        CP16(bb + 2 * G1_PLANE_B + d0, srcBb); CP16(bb + 2 * G1_PLANE_B + d1, srcBb + 16);
        CP16(bb + 3 * G1_PLANE_B + d0, srcBs); CP16(bb + 3 * G1_PLANE_B + d1, srcBs + 16);
        CP_COMMIT();
    }

    for (int kt = 0; kt < 8; kt++) {
        if (kt < 7) {
            const uint32_t bb = sbuf + ((kt + 1) % 3) * G1_BUF;
            const size_t offA = (size_t)(kt + 1) * (16384 * 64);
            const size_t offB = (size_t)(kt + 1) * (2048 * 64);
            CP16(bb + d0, srcAb + offA); CP16(bb + d1, srcAb + offA + 16);
            CP16(bb + G1_PLANE_B + d0, srcAs + offA); CP16(bb + G1_PLANE_B + d1, srcAs + offA + 16);
            CP16(bb + 2 * G1_PLANE_B + d0, srcBb + offB); CP16(bb + 2 * G1_PLANE_B + d1, srcBb + offB + 16);
            CP16(bb + 3 * G1_PLANE_B + d0, srcBs + offB); CP16(bb + 3 * G1_PLANE_B + d1, srcBs + offB + 16);
            CP_COMMIT();
            CP_WAIT1();
        } else {
            CP_WAIT0();
        }
        __syncthreads();

        const uint32_t base = sbuf + (kt % 3) * G1_BUF;
        const uint32_t sAb = base;
        const uint32_t sAs = base + G1_PLANE_B;
        const uint32_t sBb = base + 2 * G1_PLANE_B;
        const uint32_t sBs = base + 3 * G1_PLANE_B;

#pragma unroll
        for (int ks = 0; ks < 2; ks++) {
            const int kc = 2 * ks + lkc;
            const uint32_t csw = (uint32_t)((kc ^ swzL) << 4);

            uint32_t ab[4][4], as_[4][4];
#pragma unroll
            for (int mi = 0; mi < 4; mi++) {
                uint32_t ro = (uint32_t)(mw * 64 + mi * 16 + lro) * 64 + csw;
                ldsm_x4(ab[mi][0], ab[mi][1], ab[mi][2], ab[mi][3], sAb + ro);
                ldsm_x4(as_[mi][0], as_[mi][1], as_[mi][2], as_[mi][3], sAs + ro);
            }
            uint32_t bbg[2][4], bsm[2][4];
#pragma unroll
            for (int fp = 0; fp < 2; fp++) {
                uint32_t ro = (uint32_t)(nw * 32 + fp * 16 + lro) * 64 + csw;
                ldsm_x4(bbg[fp][0], bbg[fp][1], bbg[fp][2], bbg[fp][3], sBb + ro);
                ldsm_x4(bsm[fp][0], bsm[fp][1], bsm[fp][2], bsm[fp][3], sBs + ro);
            }
#pragma unroll
            for (int fp = 0; fp < 2; fp++) {
#pragma unroll
                for (int sub = 0; sub < 2; sub++) {
                    const int f = fp * 2 + sub;
                    const uint32_t b0g = bbg[fp][sub], b1g = bbg[fp][2 + sub];
                    const uint32_t b0s = bsm[fp][sub], b1s = bsm[fp][2 + sub];
#pragma unroll
                    for (int mi = 0; mi < 4; mi++) {
                        MMA_BF16(acc[mi][f], ab[mi][0], ab[mi][1], ab[mi][2], ab[mi][3], b0g, b1g);
                        MMA_BF16(acc[mi][f], as_[mi][0], as_[mi][1], as_[mi][2], as_[mi][3], b0g, b1g);
                        MMA_BF16(acc[mi][f], ab[mi][0], ab[mi][1], ab[mi][2], ab[mi][3], b0s, b1s);
                    }
                }
            }
        }
    }

#pragma unroll
    for (int f = 0; f < 4; f++) {
        const int c = j0 + nw * 32 + f * 8 + tg * 2;
        const float bw0 = bWp[c];
        const float bw1 = bWp[c + 1];
        const int h = c >> 8;
        const int o = c & 255;
#pragma unroll
        for (int mi = 0; mi < 4; mi++) {
            int r0 = m0 + mw * 64 + mi * 16 + g;
            int b0i = r0 >> 10, n0i = r0 & 1023;
            int r1 = r0 + 8;
            int b1i = r1 >> 10, n1i = r1 & 1023;
            float2 v0, v1;
            v0.x = acc[mi][f][0] + bw0; v0.y = acc[mi][f][1] + bw1;
            v1.x = acc[mi][f][2] + bw0; v1.y = acc[mi][f][3] + bw1;
            size_t i0 = ((size_t)(b0i * HH + h) * NN + n0i) * FOUT + o;
            size_t i1 = ((size_t)(b1i * HH + h) * NN + n1i) * FOUT + o;
            *(float2*)(g_Wh + i0) = v0;
            *(float2*)(g_Wh + i1) = v1;
            uint32_t u0, u1;
            PACK_BF16X2(u0, v0.x, v0.y);
            PACK_BF16X2(u1, v1.x, v1.y);
            *(uint32_t*)((char*)g_Whb + i0 * 2) = u0;
            *(uint32_t*)((char*)g_Whb + i1 * 2) = u1;
        }
    }
}

// ---------------------------------------------------------------------------
// Kernel 2: ei / ejb projections (unchanged)
// ---------------------------------------------------------------------------
__global__ void __launch_bounds__(256) score_kernel(const float* __restrict__ a1,
                                                    const float* __restrict__ a2,
                                                    const float* __restrict__ bA)
{
    const int warp = threadIdx.x >> 5;
    const int lane = threadIdx.x & 31;
    const int row = blockIdx.x * 8 + warp;
    const int h = (row >> 10) & (HH - 1);

    const float4* wr = (const float4*)(g_Wh + (size_t)row * FOUT);
    const float4* p1 = (const float4*)(a1 + h * FOUT);
    const float4* p2 = (const float4*)(a2 + h * FOUT);

    float s1 = 0.f, s2 = 0.f;
#pragma unroll
    for (int u = 0; u < 2; u++) {
        float4 v = wr[lane + u * 32];
        float4 x = p1[lane + u * 32];
        float4 y = p2[lane + u * 32];
        s1 += v.x * x.x + v.y * x.y + v.z * x.z + v.w * x.w;
        s2 += v.x * y.x + v.y * y.y + v.z * y.z + v.w * y.w;
    }
#pragma unroll
    for (int off = 16; off > 0; off >>= 1) {
        s1 += __shfl_xor_sync(0xffffffffu, s1, off);
        s2 += __shfl_xor_sync(0xffffffffu, s2, off);
    }
    if (lane == 0) {
        g_ei[row] = s1;
        g_ejb[row] = s2 + bA[h];
    }
}

// ---------------------------------------------------------------------------
// Kernel 3 (fused): per-bh sorted prefix-scan attention with 16-deep MLP
// prefetch pipelines. Identical algebra / summation order to the validated
// R10 kernel; only the memory scheduling changed.
// ---------------------------------------------------------------------------
__device__ __forceinline__ void emit_row(float* __restrict__ out,
                                         int b, int h, int i, int tid,
                                         float Ai, float Bi,
                                         float Utot, float prefU, float prefV,
                                         float ustot, float prefus, float prefvs)
{
    float l = Ai * (ustot - prefus) + Bi * prefvs;
    float x = __fdividef(Ai * (Utot - prefU) + Bi * prefV, l);
    x = fmaxf(x, 0.f);
    float y = __fdividef(1.f, 1.f + __expf(-x));
    out[(size_t)(b * NN + i) * (HH * FOUT) + h * FOUT + tid] = y;
}

__global__ void __launch_bounds__(256) attn_scan_kernel(float* __restrict__ out)
{
    __shared__ float skey[1024];
    __shared__ int   sidx[1024];
    __shared__ float ikey[1024];
    __shared__ int   iidx[1024];
    __shared__ float su[1024], sv[1024];
    __shared__ float sAi[1024], sBi[1024];
    __shared__ int   ss[1024];

    const int bh = blockIdx.x;
    const int tid = threadIdx.x;

    for (int t = tid; t < 1024; t += 256) {
        skey[t] = g_ejb[bh * 1024 + t];  sidx[t] = t;
        ikey[t] = -g_ei[bh * 1024 + t];  iidx[t] = t;
    }
    __syncthreads();

    // fused bitonic sorts: skey ascending (ej), ikey ascending (-ei)
    for (int k = 2; k <= 1024; k <<= 1) {
        for (int j = k >> 1; j > 0; j >>= 1) {
            for (int t = tid; t < 1024; t += 256) {
                int p = t ^ j;
                if (p > t) {
                    bool up = ((t & k) == 0);
                    float a = skey[t], bv = skey[p];
                    if ((a > bv) == up) {
                        skey[t] = bv; skey[p] = a;
                        int ia = sidx[t]; sidx[t] = sidx[p]; sidx[p] = ia;
                    }
                    float c = ikey[t], d = ikey[p];
                    if ((c > d) == up) {
                        ikey[t] = d; ikey[p] = c;
                        int ib = iidx[t]; iidx[t] = iidx[p]; iidx[p] = ib;
                    }
                }
            }
            __syncthreads();
        }
    }

    // per-rank exps and per-row (Ai, Bi, split point s)
    for (int t = tid; t < 1024; t += 256) {
        float e = skey[t];
        su[t] = __expf(e);
        sv[t] = __expf(ALPHA * e);
        float ei = -ikey[t];
        sAi[t] = __expf(ei);
        sBi[t] = __expf(ALPHA * ei);
        float thr = ikey[t];                 // -ei
        int lo = 0, hi = 1024;
        while (lo < hi) {
            int mid = (lo + hi) >> 1;
            if (skey[mid] <= thr) lo = mid + 1; else hi = mid;
        }
        ss[t] = lo;                          // monotone nondecreasing in t
    }
    __syncthreads();

    const __nv_bfloat16* wb = g_Whb + (size_t)bh * (NN * FOUT);

    // ---- pass A: U_total + usum_total, 16-deep prefetch pipeline ----
    float ut[4] = {0.f, 0.f, 0.f, 0.f};
    float ustot = 0.f;
    float wreg[16];
#pragma unroll
    for (int q = 0; q < 16; q++)
        wreg[q] = __bfloat162float(wb[(size_t)sidx[q] * FOUT + tid]);

    for (int rb = 0; rb < 1024; rb += 16) {
#pragma unroll
        for (int q = 0; q < 16; q++) {
            const int r = rb + q;
            float w = wreg[q];
            const int rn = r + 16;
            if (rn < 1024)
                wreg[q] = __bfloat162float(wb[(size_t)sidx[rn] * FOUT + tid]);
            ut[q & 3] = fmaf(su[r], w, ut[q & 3]);
            ustot += su[r];
        }
    }
    const float Utot = (ut[0] + ut[1]) + (ut[2] + ut[3]);

    // ---- pass B: sequential prefix sweep + inline emission, 16-deep MLP ----
    const int b = bh >> 3, h = bh & 7;
    float prefU = 0.f, prefV = 0.f, prefus = 0.f, prefvs = 0.f;
    int ep = 0;

    while (ep < 1024 && ss[ep] == 0) {       // rows entirely in U branch
        emit_row(out, b, h, iidx[ep], tid, sAi[ep], sBi[ep],
                 Utot, prefU, prefV, ustot, prefus, prefvs);
        ep++;
    }

#pragma unroll
    for (int q = 0; q < 16; q++)
        wreg[q] = __bfloat162float(wb[(size_t)sidx[q] * FOUT + tid]);

    for (int rb = 0; rb < 1024; rb += 16) {
#pragma unroll
        for (int q = 0; q < 16; q++) {
            const int r = rb + q;
            float w = wreg[q];
            const int rn = r + 16;
            if (rn < 1024)
                wreg[q] = __bfloat162float(wb[(size_t)sidx[rn] * FOUT + tid]);
            prefU = fmaf(su[r], w, prefU);
            prefV = fmaf(sv[r], w, prefV);
            prefus += su[r];
            prefvs += sv[r];
            while (ep < 1024 && ss[ep] == r + 1) {
                emit_row(out, b, h, iidx[ep], tid, sAi[ep], sBi[ep],
                         Utot, prefU, prefV, ustot, prefus, prefvs);
                ep++;
            }
        }
    }
}

// ---------------------------------------------------------------------------
extern "C" void kernel_launch(void* const* d_in, const int* in_sizes, int n_in,
                              void* d_out, int out_size)
{
    (void)in_sizes; (void)n_in; (void)out_size;
    const float* h_in = (const float*)d_in[0];
    const float* W    = (const float*)d_in[1];
    const float* bW   = (const float*)d_in[2];
    const float* a1   = (const float*)d_in[3];
    const float* a2   = (const float*)d_in[4];
    const float* bA   = (const float*)d_in[5];
    float* out = (float*)d_out;

    split_h_kernel<<<16384, 256>>>(h_in);
    split_w_kernel<<<2048, 256>>>(W);

    cudaFuncSetAttribute(gemm1_cp_kernel,
                         cudaFuncAttributeMaxDynamicSharedMemorySize, G1_SMEM);
    gemm1_cp_kernel<<<dim3(128, 16), 256, G1_SMEM>>>(bW);

    score_kernel<<<(BB * HH * NN) / 8, 256>>>(a1, a2, bA);

    attn_scan_kernel<<<BB * HH, 256>>>(out);
}

// round 12
// speedup vs baseline: 1.7691x; 1.7691x over previous
#include <cuda_runtime.h>
#include <cuda_bf16.h>
#include <stdint.h>
#include <math.h>

#define BB 16
#define NN 1024
#define FIN 256
#define FOUT 256
#define HH 8
#define ALPHA 0.2f

// Scratch (device globals; no allocations allowed)
__device__ float g_Wh[(size_t)BB * HH * NN * FOUT];
__device__ __nv_bfloat16 g_Whb[(size_t)BB * HH * NN * FOUT];
__device__ float g_ei[BB * HH * NN];
__device__ float g_ejb[BB * HH * NN];
__device__ __nv_bfloat16 g_hb[(size_t)8 * 16384 * 32];
__device__ __nv_bfloat16 g_hs[(size_t)8 * 16384 * 32];
__device__ __nv_bfloat16 g_wb[(size_t)8 * 2048 * 32];
__device__ __nv_bfloat16 g_ws[(size_t)8 * 2048 * 32];

#define MMA_BF16(c, a0, a1, a2, a3, b0, b1) \
    asm volatile("mma.sync.aligned.m16n8k16.row.col.f32.bf16.bf16.f32 " \
        "{%0,%1,%2,%3}, {%4,%5,%6,%7}, {%8,%9}, {%0,%1,%2,%3};" \
        : "+f"((c)[0]), "+f"((c)[1]), "+f"((c)[2]), "+f"((c)[3]) \
        : "r"(a0), "r"(a1), "r"(a2), "r"(a3), "r"(b0), "r"(b1))

#define PACK_BF16X2(r, lo, hi) \
    asm("cvt.rn.bf16x2.f32 %0, %1, %2;" : "=r"(r) : "f"(hi), "f"(lo))

#define CP16(dst, src) \
    asm volatile("cp.async.cg.shared.global [%0], [%1], 16;" :: "r"(dst), "l"(src) : "memory")
#define CP_COMMIT() asm volatile("cp.async.commit_group;" ::: "memory")
#define CP_WAIT1()  asm volatile("cp.async.wait_group 1;" ::: "memory")
#define CP_WAIT0()  asm volatile("cp.async.wait_group 0;" ::: "memory")

__device__ __forceinline__ uint32_t smem_u32(const void* p) {
    uint32_t a;
    asm("{ .reg .u64 t; cvta.to.shared.u64 t, %1; cvt.u32.u64 %0, t; }"
        : "=r"(a) : "l"(p));
    return a;
}
__device__ __forceinline__ void ldsm_x4(uint32_t& r0, uint32_t& r1,
                                        uint32_t& r2, uint32_t& r3, uint32_t addr) {
    asm volatile("ldmatrix.sync.aligned.m8n8.x4.shared.b16 {%0,%1,%2,%3}, [%4];"
                 : "=r"(r0), "=r"(r1), "=r"(r2), "=r"(r3) : "r"(addr));
}
__device__ __forceinline__ void ldsm_x4_t(uint32_t& r0, uint32_t& r1,
                                          uint32_t& r2, uint32_t& r3, uint32_t addr) {
    asm volatile("ldmatrix.sync.aligned.m8n8.x4.trans.shared.b16 {%0,%1,%2,%3}, [%4];"
                 : "=r"(r0), "=r"(r1), "=r"(r2), "=r"(r3) : "r"(addr));
}

// ---------------------------------------------------------------------------
// Prep: split fp32 -> big/small bf16, k-tiled [kt][row][32]
// ---------------------------------------------------------------------------
__global__ void split_h_kernel(const float* __restrict__ src)
{
    const int m = blockIdx.x;
    const int k = threadIdx.x;
    float x = src[(size_t)m * 256 + k];
    __nv_bfloat16 b = __float2bfloat16(x);
    __nv_bfloat16 s = __float2bfloat16(x - __bfloat162float(b));
    size_t idx = ((size_t)(k >> 5) * 16384 + m) * 32 + (k & 31);
    g_hb[idx] = b;
    g_hs[idx] = s;
}
__global__ void split_w_kernel(const float* __restrict__ src)
{
    const int j = blockIdx.x;
    const int k = threadIdx.x;
    float x = src[(size_t)j * 256 + k];
    __nv_bfloat16 b = __float2bfloat16(x);
    __nv_bfloat16 s = __float2bfloat16(x - __bfloat162float(b));
    size_t idx = ((size_t)(k >> 5) * 2048 + j) * 32 + (k & 31);
    g_wb[idx] = b;
    g_ws[idx] = s;
}

// ---------------------------------------------------------------------------
// Kernel 1: Wh = h @ W^T + bW via 3xBF16 m16n8k16 + cp.async (unchanged R8)
// ---------------------------------------------------------------------------
#define G1_PLANE_B 8192
#define G1_BUF (4 * G1_PLANE_B)
#define G1_SMEM (3 * G1_BUF)

__global__ void __launch_bounds__(256, 2) gemm1_cp_kernel(const float* __restrict__ bWp)
{
    extern __shared__ char gsm[];
    const uint32_t sbuf = smem_u32(gsm);

    const int tid  = threadIdx.x;
    const int lane = tid & 31;
    const int wid  = tid >> 5;
    const int mw   = wid & 1;
    const int nw   = wid >> 1;
    const int tg   = lane & 3;
    const int g    = lane >> 2;
    const int m0   = blockIdx.x * 128;
    const int j0   = blockIdx.y * 128;

    const int lrow = tid & 127;
    const int kh   = tid >> 7;
    const int swzr = (lrow & 3) ^ ((lrow >> 2) & 3);
    const uint32_t d0 = (uint32_t)lrow * 64 + (((2 * kh)     ^ swzr) << 4);
    const uint32_t d1 = (uint32_t)lrow * 64 + (((2 * kh + 1) ^ swzr) << 4);
    const char* srcAb = (const char*)g_hb + ((size_t)(m0 + lrow)) * 64 + kh * 32;
    const char* srcAs = (const char*)g_hs + ((size_t)(m0 + lrow)) * 64 + kh * 32;
    const char* srcBb = (const char*)g_wb + ((size_t)(j0 + lrow)) * 64 + kh * 32;
    const char* srcBs = (const char*)g_ws + ((size_t)(j0 + lrow)) * 64 + kh * 32;

    const int lro  = (lane & 7) + ((lane >> 3) & 1) * 8;
    const int lkc  = lane >> 4;
    const int swzL = (lro & 3) ^ ((lro >> 2) & 3);

    float acc[4][4][4];
#pragma unroll
    for (int mi = 0; mi < 4; mi++)
#pragma unroll
        for (int f = 0; f < 4; f++)
#pragma unroll
            for (int c = 0; c < 4; c++) acc[mi][f][c] = 0.f;

    {
        const uint32_t bb = sbuf;
        CP16(bb + d0, srcAb); CP16(bb + d1, srcAb + 16);
        CP16(bb + G1_PLANE_B + d0, srcAs); CP16(bb + G1_PLANE_B + d1, srcAs + 16);
        CP16(bb + 2 * G1_PLANE_B + d0, srcBb); CP16(bb + 2 * G1_PLANE_B + d1, srcBb + 16);
        CP16(bb + 3 * G1_PLANE_B + d0, srcBs); CP16(bb + 3 * G1_PLANE_B + d1, srcBs + 16);
        CP_COMMIT();
    }

    for (int kt = 0; kt < 8; kt++) {
        if (kt < 7) {
            const uint32_t bb = sbuf + ((kt + 1) % 3) * G1_BUF;
            const size_t offA = (size_t)(kt + 1) * (16384 * 64);
            const size_t offB = (size_t)(kt + 1) * (2048 * 64);
            CP16(bb + d0, srcAb + offA); CP16(bb + d1, srcAb + offA + 16);
            CP16(bb + G1_PLANE_B + d0, srcAs + offA); CP16(bb + G1_PLANE_B + d1, srcAs + offA + 16);
            CP16(bb + 2 * G1_PLANE_B + d0, srcBb + offB); CP16(bb + 2 * G1_PLANE_B + d1, srcBb + offB + 16);
            CP16(bb + 3 * G1_PLANE_B + d0, srcBs + offB); CP16(bb + 3 * G1_PLANE_B + d1, srcBs + offB + 16);
            CP_COMMIT();
            CP_WAIT1();
        } else {
            CP_WAIT0();
        }
        __syncthreads();

        const uint32_t base = sbuf + (kt % 3) * G1_BUF;
        const uint32_t sAb = base;
        const uint32_t sAs = base + G1_PLANE_B;
        const uint32_t sBb = base + 2 * G1_PLANE_B;
        const uint32_t sBs = base + 3 * G1_PLANE_B;

#pragma unroll
        for (int ks = 0; ks < 2; ks++) {
            const int kc = 2 * ks + lkc;
            const uint32_t csw = (uint32_t)((kc ^ swzL) << 4);

            uint32_t ab[4][4], as_[4][4];
#pragma unroll
            for (int mi = 0; mi < 4; mi++) {
                uint32_t ro = (uint32_t)(mw * 64 + mi * 16 + lro) * 64 + csw;
                ldsm_x4(ab[mi][0], ab[mi][1], ab[mi][2], ab[mi][3], sAb + ro);
                ldsm_x4(as_[mi][0], as_[mi][1], as_[mi][2], as_[mi][3], sAs + ro);
            }
            uint32_t bbg[2][4], bsm[2][4];
#pragma unroll
            for (int fp = 0; fp < 2; fp++) {
                uint32_t ro = (uint32_t)(nw * 32 + fp * 16 + lro) * 64 + csw;
                ldsm_x4(bbg[fp][0], bbg[fp][1], bbg[fp][2], bbg[fp][3], sBb + ro);
                ldsm_x4(bsm[fp][0], bsm[fp][1], bsm[fp][2], bsm[fp][3], sBs + ro);
            }
#pragma unroll
            for (int fp = 0; fp < 2; fp++) {
#pragma unroll
                for (int sub = 0; sub < 2; sub++) {
                    const int f = fp * 2 + sub;
                    const uint32_t b0g = bbg[fp][sub], b1g = bbg[fp][2 + sub];
                    const uint32_t b0s = bsm[fp][sub], b1s = bsm[fp][2 + sub];
#pragma unroll
                    for (int mi = 0; mi < 4; mi++) {
                        MMA_BF16(acc[mi][f], ab[mi][0], ab[mi][1], ab[mi][2], ab[mi][3], b0g, b1g);
                        MMA_BF16(acc[mi][f], as_[mi][0], as_[mi][1], as_[mi][2], as_[mi][3], b0g, b1g);
                        MMA_BF16(acc[mi][f], ab[mi][0], ab[mi][1], ab[mi][2], ab[mi][3], b0s, b1s);
                    }
                }
            }
        }
    }

#pragma unroll
    for (int f = 0; f < 4; f++) {
        const int c = j0 + nw * 32 + f * 8 + tg * 2;
        const float bw0 = bWp[c];
        const float bw1 = bWp[c + 1];
        const int h = c >> 8;
        const int o = c & 255;
#pragma unroll
        for (int mi = 0; mi < 4; mi++) {
            int r0 = m0 + mw * 64 + mi * 16 + g;
            int b0i = r0 >> 10, n0i = r0 & 1023;
            int r1 = r0 + 8;
            int b1i = r1 >> 10, n1i = r1 & 1023;
            float2 v0, v1;
            v0.x = acc[mi][f][0] + bw0; v0.y = acc[mi][f][1] + bw1;
            v1.x = acc[mi][f][2] + bw0; v1.y = acc[mi][f][3] + bw1;
            size_t i0 = ((size_t)(b0i * HH + h) * NN + n0i) * FOUT + o;
            size_t i1 = ((size_t)(b1i * HH + h) * NN + n1i) * FOUT + o;
            *(float2*)(g_Wh + i0) = v0;
            *(float2*)(g_Wh + i1) = v1;
            uint32_t u0, u1;
            PACK_BF16X2(u0, v0.x, v0.y);
            PACK_BF16X2(u1, v1.x, v1.y);
            *(uint32_t*)((char*)g_Whb + i0 * 2) = u0;
            *(uint32_t*)((char*)g_Whb + i1 * 2) = u1;
        }
    }
}

// ---------------------------------------------------------------------------
// Kernel 2: ei / ejb projections (unchanged)
// ---------------------------------------------------------------------------
__global__ void __launch_bounds__(256) score_kernel(const float* __restrict__ a1,
                                                    const float* __restrict__ a2,
                                                    const float* __restrict__ bA)
{
    const int warp = threadIdx.x >> 5;
    const int lane = threadIdx.x & 31;
    const int row = blockIdx.x * 8 + warp;
    const int h = (row >> 10) & (HH - 1);

    const float4* wr = (const float4*)(g_Wh + (size_t)row * FOUT);
    const float4* p1 = (const float4*)(a1 + h * FOUT);
    const float4* p2 = (const float4*)(a2 + h * FOUT);

    float s1 = 0.f, s2 = 0.f;
#pragma unroll
    for (int u = 0; u < 2; u++) {
        float4 v = wr[lane + u * 32];
        float4 x = p1[lane + u * 32];
        float4 y = p2[lane + u * 32];
        s1 += v.x * x.x + v.y * x.y + v.z * x.z + v.w * x.w;
        s2 += v.x * y.x + v.y * y.y + v.z * y.z + v.w * y.w;
    }
#pragma unroll
    for (int off = 16; off > 0; off >>= 1) {
        s1 += __shfl_xor_sync(0xffffffffu, s1, off);
        s2 += __shfl_xor_sync(0xffffffffu, s2, off);
    }
    if (lane == 0) {
        g_ei[row] = s1;
        g_ejb[row] = s2 + bA[h];
    }
}

// ---------------------------------------------------------------------------
// Kernel 3: attention bf16 m16n8k16 + cp.async (R8 math), 64-row CTAs,
// 256 threads = 8 warps (4M x 2N), 2 CTAs/SM for phase overlap.
// B tile layout/swizzle identical to R8 ([j(32)][512B], chunk c ^ (j&7)).
// ---------------------------------------------------------------------------
#define BUFB_BYTES 16384
#define ATTN_SMEM (3 * BUFB_BYTES + NN * 16 + 512)

__global__ void __launch_bounds__(256, 2) attn_cp_kernel(float* __restrict__ out)
{
    extern __shared__ char smc[];
    float4* equad = (float4*)(smc + 3 * BUFB_BYTES);
    float*  linv  = (float*)(smc + 3 * BUFB_BYTES + NN * 16);
    const uint32_t sbase = smem_u32(smc);

    const int tid  = threadIdx.x;
    const int lane = tid & 31;
    const int wid  = tid >> 5;
    const int mw   = wid & 3;          // 4 M-warps -> 64 rows
    const int nw   = wid >> 2;         // 2 N-warps -> 256 cols
    const int g    = lane >> 2;
    const int tg   = lane & 3;
    const int bh   = blockIdx.x >> 4;
    const int it   = blockIdx.x & 15;  // 16 row-tiles of 64

    // loader mapping: thread -> (j, 4 chunks of 16B)
    const int ldj = tid >> 3;              // 0..31
    const int ldc = (tid & 7) * 4;         // chunks ldc..ldc+3
    const char* whbB = (const char*)g_Whb + (size_t)bh * (NN * FOUT) * 2;
    uint32_t dst4[4];
#pragma unroll
    for (int ci = 0; ci < 4; ci++)
        dst4[ci] = (uint32_t)ldj * 512 + (((ldc + ci) ^ (ldj & 7)) << 4);

    // stage jt=0
    {
        const char* s = whbB + ((size_t)ldj) * 512 + ldc * 16;
#pragma unroll
        for (int ci = 0; ci < 4; ci++)
            CP16(sbase + dst4[ci], s + ci * 16);
        CP_COMMIT();
    }

    // --- prologue: ej quads ---
    const float* ejg = g_ejb + (size_t)bh * NN;
#pragma unroll
    for (int q = 0; q < 4; q++) {
        int j = tid + q * 256;
        float e = ejg[j];
        equad[j] = make_float4(e, __expf(e), __expf(ALPHA * e), 0.f);
    }

    const int r1 = mw * 16 + g;            // 0..63
    const float ei1 = g_ei[(size_t)bh * NN + it * 64 + r1];
    const float ei2 = g_ei[(size_t)bh * NN + it * 64 + r1 + 8];
    const float Ai1 = __expf(ei1), Bi1 = __expf(ALPHA * ei1);
    const float Ai2 = __expf(ei2), Bi2 = __expf(ALPHA * ei2);

    float acc[16][4];
#pragma unroll
    for (int f = 0; f < 16; f++)
#pragma unroll
        for (int c = 0; c < 4; c++) acc[f][c] = 0.f;

    __syncthreads();   // equad visible before first aP compute

    float lsum1 = 0.f, lsum2 = 0.f;

    for (int jt = 0; jt < 32; jt++) {
        if (jt < 31) {
            const uint32_t bb = sbase + ((jt + 1) % 3) * BUFB_BYTES;
            const char* s = whbB + ((size_t)(jt + 1) * 32 + ldj) * 512 + ldc * 16;
#pragma unroll
            for (int ci = 0; ci < 4; ci++)
                CP16(bb + dst4[ci], s + ci * 16);
            CP_COMMIT();
        }

        // --- P fragments (only reads equad; overlaps cp.async latency) ---
        uint32_t aP[2][4];
#pragma unroll
        for (int s = 0; s < 4; s++) {
            int jl = jt * 32 + 2 * tg + 8 * s;
            float4 q0 = equad[jl];
            float4 q1 = equad[jl + 1];
            float e, pa1, pb1, pa2, pb2;
            e = ei1 + q0.x; pa1 = (e > 0.f) ? Ai1 * q0.y : Bi1 * q0.z;
            e = ei1 + q1.x; pb1 = (e > 0.f) ? Ai1 * q1.y : Bi1 * q1.z;
            e = ei2 + q0.x; pa2 = (e > 0.f) ? Ai2 * q0.y : Bi2 * q0.z;
            e = ei2 + q1.x; pb2 = (e > 0.f) ? Ai2 * q1.y : Bi2 * q1.z;
            if (nw == 0) { lsum1 += pa1 + pb1; lsum2 += pa2 + pb2; }
            uint32_t u1, u2;
            PACK_BF16X2(u1, pa1, pb1);
            PACK_BF16X2(u2, pa2, pb2);
            int kc = s >> 1;
            if ((s & 1) == 0) { aP[kc][0] = u1; aP[kc][1] = u2; }
            else              { aP[kc][2] = u1; aP[kc][3] = u2; }
        }

        if (jt < 31) CP_WAIT1(); else CP_WAIT0();
        __syncthreads();   // buf[jt%3] complete + prior readers done

        const uint32_t bufa = sbase + (jt % 3) * BUFB_BYTES + lane * 512;
        const int key = lane & 7;
#pragma unroll
        for (int f = 0; f < 16; f++) {
            int c = nw * 16 + f;
            uint32_t b0, b1, b2, b3;
            ldsm_x4_t(b0, b1, b2, b3, bufa + ((c ^ key) * 16));
            MMA_BF16(acc[f], aP[0][0], aP[0][1], aP[0][2], aP[0][3], b0, b1);
            MMA_BF16(acc[f], aP[1][0], aP[1][1], aP[1][2], aP[1][3], b2, b3);
        }
    }

    // --- l reduction (nw==0 warps cover all 64 rows) ---
    if (nw == 0) {
        lsum1 += __shfl_xor_sync(0xffffffffu, lsum1, 1);
        lsum1 += __shfl_xor_sync(0xffffffffu, lsum1, 2);
        lsum2 += __shfl_xor_sync(0xffffffffu, lsum2, 1);
        lsum2 += __shfl_xor_sync(0xffffffffu, lsum2, 2);
        if (tg == 0) {
            linv[r1] = 1.f / lsum1;
            linv[r1 + 8] = 1.f / lsum2;
        }
    }
    __syncthreads();

    const float li1 = linv[r1];
    const float li2 = linv[r1 + 8];
    const int b = bh >> 3, h = bh & 7;
    float* o1 = out + (size_t)(b * NN + it * 64 + r1) * (HH * FOUT)
                    + h * FOUT + nw * 128;
    float* o2 = o1 + (size_t)8 * (HH * FOUT);

#pragma unroll
    for (int f = 0; f < 16; f++) {
        int oc2 = f * 8 + tg * 2;
        float x0 = fmaxf(acc[f][0] * li1, 0.f);
        float x1 = fmaxf(acc[f][1] * li1, 0.f);
        float x2 = fmaxf(acc[f][2] * li2, 0.f);
        float x3 = fmaxf(acc[f][3] * li2, 0.f);
        float2 v1, v2;
        v1.x = 1.f / (1.f + __expf(-x0));
        v1.y = 1.f / (1.f + __expf(-x1));
        v2.x = 1.f / (1.f + __expf(-x2));
        v2.y = 1.f / (1.f + __expf(-x3));
        *(float2*)(o1 + oc2) = v1;
        *(float2*)(o2 + oc2) = v2;
    }
}

// ---------------------------------------------------------------------------
extern "C" void kernel_launch(void* const* d_in, const int* in_sizes, int n_in,
                              void* d_out, int out_size)
{
    (void)in_sizes; (void)n_in; (void)out_size;
    const float* h_in = (const float*)d_in[0];
    const float* W    = (const float*)d_in[1];
    const float* bW   = (const float*)d_in[2];
    const float* a1   = (const float*)d_in[3];
    const float* a2   = (const float*)d_in[4];
    const float* bA   = (const float*)d_in[5];
    float* out = (float*)d_out;

    split_h_kernel<<<16384, 256>>>(h_in);
    split_w_kernel<<<2048, 256>>>(W);

    cudaFuncSetAttribute(gemm1_cp_kernel,
                         cudaFuncAttributeMaxDynamicSharedMemorySize, G1_SMEM);
    gemm1_cp_kernel<<<dim3(128, 16), 256, G1_SMEM>>>(bW);

    score_kernel<<<(BB * HH * NN) / 8, 256>>>(a1, a2, bA);

    cudaFuncSetAttribute(attn_cp_kernel,
                         cudaFuncAttributeMaxDynamicSharedMemorySize, ATTN_SMEM);
    attn_cp_kernel<<<BB * HH * 16, 256, ATTN_SMEM>>>(out);
}

// round 13
// speedup vs baseline: 2.0731x; 1.1719x over previous
#include <cuda_runtime.h>
#include <cuda_bf16.h>
#include <stdint.h>
#include <math.h>

#define BB 16
#define NN 1024
#define FIN 256
#define FOUT 256
#define HH 8
#define ALPHA 0.2f

// Scratch (device globals; no allocations allowed)
__device__ float g_Wh[(size_t)BB * HH * NN * FOUT];
__device__ __nv_bfloat16 g_Whb[(size_t)BB * HH * NN * FOUT];
__device__ float g_ei[BB * HH * NN];
__device__ float g_ejb[BB * HH * NN];
__device__ __nv_bfloat16 g_hb[(size_t)8 * 16384 * 32];
__device__ __nv_bfloat16 g_hs[(size_t)8 * 16384 * 32];
__device__ __nv_bfloat16 g_wb[(size_t)8 * 2048 * 32];
__device__ __nv_bfloat16 g_ws[(size_t)8 * 2048 * 32];

#define MMA_BF16(c, a0, a1, a2, a3, b0, b1) \
    asm volatile("mma.sync.aligned.m16n8k16.row.col.f32.bf16.bf16.f32 " \
        "{%0,%1,%2,%3}, {%4,%5,%6,%7}, {%8,%9}, {%0,%1,%2,%3};" \
        : "+f"((c)[0]), "+f"((c)[1]), "+f"((c)[2]), "+f"((c)[3]) \
        : "r"(a0), "r"(a1), "r"(a2), "r"(a3), "r"(b0), "r"(b1))

#define PACK_BF16X2(r, lo, hi) \
    asm("cvt.rn.bf16x2.f32 %0, %1, %2;" : "=r"(r) : "f"(hi), "f"(lo))

#define CP16(dst, src) \
    asm volatile("cp.async.cg.shared.global [%0], [%1], 16;" :: "r"(dst), "l"(src) : "memory")
#define CP_COMMIT() asm volatile("cp.async.commit_group;" ::: "memory")
#define CP_WAIT0()  asm volatile("cp.async.wait_group 0;" ::: "memory")
#define CP_WAIT1()  asm volatile("cp.async.wait_group 1;" ::: "memory")
#define CP_WAIT2()  asm volatile("cp.async.wait_group 2;" ::: "memory")
#define CP_WAIT3()  asm volatile("cp.async.wait_group 3;" ::: "memory")

__device__ __forceinline__ uint32_t smem_u32(const void* p) {
    uint32_t a;
    asm("{ .reg .u64 t; cvta.to.shared.u64 t, %1; cvt.u32.u64 %0, t; }"
        : "=r"(a) : "l"(p));
    return a;
}
__device__ __forceinline__ void ldsm_x4(uint32_t& r0, uint32_t& r1,
                                        uint32_t& r2, uint32_t& r3, uint32_t addr) {
    asm volatile("ldmatrix.sync.aligned.m8n8.x4.shared.b16 {%0,%1,%2,%3}, [%4];"
                 : "=r"(r0), "=r"(r1), "=r"(r2), "=r"(r3) : "r"(addr));
}

// ---------------------------------------------------------------------------
// Prep: split fp32 -> big/small bf16, k-tiled [kt][row][32]
// ---------------------------------------------------------------------------
__global__ void split_h_kernel(const float* __restrict__ src)
{
    const int m = blockIdx.x;
    const int k = threadIdx.x;
    float x = src[(size_t)m * 256 + k];
    __nv_bfloat16 b = __float2bfloat16(x);
    __nv_bfloat16 s = __float2bfloat16(x - __bfloat162float(b));
    size_t idx = ((size_t)(k >> 5) * 16384 + m) * 32 + (k & 31);
    g_hb[idx] = b;
    g_hs[idx] = s;
}
__global__ void split_w_kernel(const float* __restrict__ src)
{
    const int j = blockIdx.x;
    const int k = threadIdx.x;
    float x = src[(size_t)j * 256 + k];
    __nv_bfloat16 b = __float2bfloat16(x);
    __nv_bfloat16 s = __float2bfloat16(x - __bfloat162float(b));
    size_t idx = ((size_t)(k >> 5) * 2048 + j) * 32 + (k & 31);
    g_wb[idx] = b;
    g_ws[idx] = s;
}

// ---------------------------------------------------------------------------
// Kernel 1: Wh = h @ W^T + bW via 3xBF16 m16n8k16 + cp.async (unchanged R8)
// ---------------------------------------------------------------------------
#define G1_PLANE_B 8192
#define G1_BUF (4 * G1_PLANE_B)
#define G1_SMEM (3 * G1_BUF)

__global__ void __launch_bounds__(256, 2) gemm1_cp_kernel(const float* __restrict__ bWp)
{
    extern __shared__ char gsm[];
    const uint32_t sbuf = smem_u32(gsm);

    const int tid  = threadIdx.x;
    const int lane = tid & 31;
    const int wid  = tid >> 5;
    const int mw   = wid & 1;
    const int nw   = wid >> 1;
    const int tg   = lane & 3;
    const int g    = lane >> 2;
    const int m0   = blockIdx.x * 128;
    const int j0   = blockIdx.y * 128;

    const int lrow = tid & 127;
    const int kh   = tid >> 7;
    const int swzr = (lrow & 3) ^ ((lrow >> 2) & 3);
    const uint32_t d0 = (uint32_t)lrow * 64 + (((2 * kh)     ^ swzr) << 4);
    const uint32_t d1 = (uint32_t)lrow * 64 + (((2 * kh + 1) ^ swzr) << 4);
    const char* srcAb = (const char*)g_hb + ((size_t)(m0 + lrow)) * 64 + kh * 32;
    const char* srcAs = (const char*)g_hs + ((size_t)(m0 + lrow)) * 64 + kh * 32;
    const char* srcBb = (const char*)g_wb + ((size_t)(j0 + lrow)) * 64 + kh * 32;
    const char* srcBs = (const char*)g_ws + ((size_t)(j0 + lrow)) * 64 + kh * 32;

    const int lro  = (lane & 7) + ((lane >> 3) & 1) * 8;
    const int lkc  = lane >> 4;
    const int swzL = (lro & 3) ^ ((lro >> 2) & 3);

    float acc[4][4][4];
#pragma unroll
    for (int mi = 0; mi < 4; mi++)
#pragma unroll
        for (int f = 0; f < 4; f++)
#pragma unroll
            for (int c = 0; c < 4; c++) acc[mi][f][c] = 0.f;

    {
        const uint32_t bb = sbuf;
        CP16(bb + d0, srcAb); CP16(bb + d1, srcAb + 16);
        CP16(bb + G1_PLANE_B + d0, srcAs); CP16(bb + G1_PLANE_B + d1, srcAs + 16);
        CP16(bb + 2 * G1_PLANE_B + d0, srcBb); CP16(bb + 2 * G1_PLANE_B + d1, srcBb + 16);
        CP16(bb + 3 * G1_PLANE_B + d0, srcBs); CP16(bb + 3 * G1_PLANE_B + d1, srcBs + 16);
        CP_COMMIT();
    }

    for (int kt = 0; kt < 8; kt++) {
        if (kt < 7) {
            const uint32_t bb = sbuf + ((kt + 1) % 3) * G1_BUF;
            const size_t offA = (size_t)(kt + 1) * (16384 * 64);
            const size_t offB = (size_t)(kt + 1) * (2048 * 64);
            CP16(bb + d0, srcAb + offA); CP16(bb + d1, srcAb + offA + 16);
            CP16(bb + G1_PLANE_B + d0, srcAs + offA); CP16(bb + G1_PLANE_B + d1, srcAs + offA + 16);
            CP16(bb + 2 * G1_PLANE_B + d0, srcBb + offB); CP16(bb + 2 * G1_PLANE_B + d1, srcBb + offB + 16);
            CP16(bb + 3 * G1_PLANE_B + d0, srcBs + offB); CP16(bb + 3 * G1_PLANE_B + d1, srcBs + offB + 16);
            CP_COMMIT();
            CP_WAIT1();
        } else {
            CP_WAIT0();
        }
        __syncthreads();

        const uint32_t base = sbuf + (kt % 3) * G1_BUF;
        const uint32_t sAb = base;
        const uint32_t sAs = base + G1_PLANE_B;
        const uint32_t sBb = base + 2 * G1_PLANE_B;
        const uint32_t sBs = base + 3 * G1_PLANE_B;

#pragma unroll
        for (int ks = 0; ks < 2; ks++) {
            const int kc = 2 * ks + lkc;
            const uint32_t csw = (uint32_t)((kc ^ swzL) << 4);

            uint32_t ab[4][4], as_[4][4];
#pragma unroll
            for (int mi = 0; mi < 4; mi++) {
                uint32_t ro = (uint32_t)(mw * 64 + mi * 16 + lro) * 64 + csw;
                ldsm_x4(ab[mi][0], ab[mi][1], ab[mi][2], ab[mi][3], sAb + ro);
                ldsm_x4(as_[mi][0], as_[mi][1], as_[mi][2], as_[mi][3], sAs + ro);
            }
            uint32_t bbg[2][4], bsm[2][4];
#pragma unroll
            for (int fp = 0; fp < 2; fp++) {
                uint32_t ro = (uint32_t)(nw * 32 + fp * 16 + lro) * 64 + csw;
                ldsm_x4(bbg[fp][0], bbg[fp][1], bbg[fp][2], bbg[fp][3], sBb + ro);
                ldsm_x4(bsm[fp][0], bsm[fp][1], bsm[fp][2], bsm[fp][3], sBs + ro);
            }
#pragma unroll
            for (int fp = 0; fp < 2; fp++) {
#pragma unroll
                for (int sub = 0; sub < 2; sub++) {
                    const int f = fp * 2 + sub;
                    const uint32_t b0g = bbg[fp][sub], b1g = bbg[fp][2 + sub];
                    const uint32_t b0s = bsm[fp][sub], b1s = bsm[fp][2 + sub];
#pragma unroll
                    for (int mi = 0; mi < 4; mi++) {
                        MMA_BF16(acc[mi][f], ab[mi][0], ab[mi][1], ab[mi][2], ab[mi][3], b0g, b1g);
                        MMA_BF16(acc[mi][f], as_[mi][0], as_[mi][1], as_[mi][2], as_[mi][3], b0g, b1g);
                        MMA_BF16(acc[mi][f], ab[mi][0], ab[mi][1], ab[mi][2], ab[mi][3], b0s, b1s);
                    }
                }
            }
        }
    }

#pragma unroll
    for (int f = 0; f < 4; f++) {
        const int c = j0 + nw * 32 + f * 8 + tg * 2;
        const float bw0 = bWp[c];
        const float bw1 = bWp[c + 1];
        const int h = c >> 8;
        const int o = c & 255;
#pragma unroll
        for (int mi = 0; mi < 4; mi++) {
            int r0 = m0 + mw * 64 + mi * 16 + g;
            int b0i = r0 >> 10, n0i = r0 & 1023;
            int r1 = r0 + 8;
            int b1i = r1 >> 10, n1i = r1 & 1023;
            float2 v0, v1;
            v0.x = acc[mi][f][0] + bw0; v0.y = acc[mi][f][1] + bw1;
            v1.x = acc[mi][f][2] + bw0; v1.y = acc[mi][f][3] + bw1;
            size_t i0 = ((size_t)(b0i * HH + h) * NN + n0i) * FOUT + o;
            size_t i1 = ((size_t)(b1i * HH + h) * NN + n1i) * FOUT + o;
            *(float2*)(g_Wh + i0) = v0;
            *(float2*)(g_Wh + i1) = v1;
            uint32_t u0, u1;
            PACK_BF16X2(u0, v0.x, v0.y);
            PACK_BF16X2(u1, v1.x, v1.y);
            *(uint32_t*)((char*)g_Whb + i0 * 2) = u0;
            *(uint32_t*)((char*)g_Whb + i1 * 2) = u1;
        }
    }
}

// ---------------------------------------------------------------------------
// Kernel 2: ei / ejb projections (unchanged)
// ---------------------------------------------------------------------------
__global__ void __launch_bounds__(256) score_kernel(const float* __restrict__ a1,
                                                    const float* __restrict__ a2,
                                                    const float* __restrict__ bA)
{
    const int warp = threadIdx.x >> 5;
    const int lane = threadIdx.x & 31;
    const int row = blockIdx.x * 8 + warp;
    const int h = (row >> 10) & (HH - 1);

    const float4* wr = (const float4*)(g_Wh + (size_t)row * FOUT);
    const float4* p1 = (const float4*)(a1 + h * FOUT);
    const float4* p2 = (const float4*)(a2 + h * FOUT);

    float s1 = 0.f, s2 = 0.f;
#pragma unroll
    for (int u = 0; u < 2; u++) {
        float4 v = wr[lane + u * 32];
        float4 x = p1[lane + u * 32];
        float4 y = p2[lane + u * 32];
        s1 += v.x * x.x + v.y * x.y + v.z * x.z + v.w * x.w;
        s2 += v.x * y.x + v.y * y.y + v.z * y.z + v.w * y.w;
    }
#pragma unroll
    for (int off = 16; off > 0; off >>= 1) {
        s1 += __shfl_xor_sync(0xffffffffu, s1, off);
        s2 += __shfl_xor_sync(0xffffffffu, s2, off);
    }
    if (lane == 0) {
        g_ei[row] = s1;
        g_ejb[row] = s2 + bA[h];
    }
}

// ---------------------------------------------------------------------------
// Kernel 3 (scan v3): per-bh sorted prefix-scan attention.
// Sweep reads Whb rows from smem chunks staged by a 4-buffer cp.async
// pipeline (gather via sidx). Same algebra as R9/R10 (validated).
// smem layout (bytes):
//   [0, 65536)          4 x 16KB chunk buffers
//   [65536 ...)         skey, sidx, ikey, iidx, su, sv, sAi, sBi, ss, slinv (4KB each)
//   [106496, 110624)    pus[1025] (+pad)
//   [110624, 114752)    pvs[1025] (+pad)
//   [114752, 115776)    red[256]
// ---------------------------------------------------------------------------
#define ASCAN_SMEM 115776

__device__ __forceinline__ void pipe_wait(int c) {
    int rem = 31 - c;
    if (rem >= 3)      CP_WAIT3();
    else if (rem == 2) CP_WAIT2();
    else if (rem == 1) CP_WAIT1();
    else               CP_WAIT0();
}

__global__ void __launch_bounds__(256) attn_scan2_kernel(float* __restrict__ out)
{
    extern __shared__ char sm[];
    float* skey  = (float*)(sm + 65536);
    int*   sidx  = (int*)  (sm + 69632);
    float* ikey  = (float*)(sm + 73728);
    int*   iidx  = (int*)  (sm + 77824);
    float* su    = (float*)(sm + 81920);
    float* sv    = (float*)(sm + 86016);
    float* sAi   = (float*)(sm + 90112);
    float* sBi   = (float*)(sm + 94208);
    int*   ss    = (int*)  (sm + 98304);
    float* slinv = (float*)(sm + 102400);
    float* pus   = (float*)(sm + 106496);   // 1025 entries
    float* pvs   = (float*)(sm + 110624);   // 1025 entries
    float* red   = (float*)(sm + 114752);   // 256
    const uint32_t sbase = smem_u32(sm);

    const int bh = blockIdx.x;
    const int tid = threadIdx.x;
    const char* whbB = (const char*)g_Whb + (size_t)bh * (NN * FOUT) * 2;

    for (int t = tid; t < 1024; t += 256) {
        skey[t] = g_ejb[bh * 1024 + t];  sidx[t] = t;
        ikey[t] = -g_ei[bh * 1024 + t];  iidx[t] = t;
    }
    __syncthreads();

    // fused dual bitonic sort (ascending)
    for (int k = 2; k <= 1024; k <<= 1) {
        for (int j = k >> 1; j > 0; j >>= 1) {
            for (int t = tid; t < 1024; t += 256) {
                int p = t ^ j;
                if (p > t) {
                    bool up = ((t & k) == 0);
                    float a = skey[t], bv = skey[p];
                    if ((a > bv) == up) {
                        skey[t] = bv; skey[p] = a;
                        int ia = sidx[t]; sidx[t] = sidx[p]; sidx[p] = ia;
                    }
                    float c = ikey[t], d = ikey[p];
                    if ((c > d) == up) {
                        ikey[t] = d; ikey[p] = c;
                        int ib = iidx[t]; iidx[t] = iidx[p]; iidx[p] = ib;
                    }
                }
            }
            __syncthreads();
        }
    }

    // per-rank exps and per-row (Ai, Bi, split s)
    for (int t = tid; t < 1024; t += 256) {
        float e = skey[t];
        su[t] = __expf(e);
        sv[t] = __expf(ALPHA * e);
        float ei = -ikey[t];
        sAi[t] = __expf(ei);
        sBi[t] = __expf(ALPHA * ei);
        float thr = ikey[t];
        int lo = 0, hi = 1024;
        while (lo < hi) {
            int mid = (lo + hi) >> 1;
            if (skey[mid] <= thr) lo = mid + 1; else hi = mid;
        }
        ss[t] = lo;
    }
    __syncthreads();

    // scalar exclusive scans: su -> pus, sv -> pvs
    {
        float a0 = su[4 * tid], a1 = su[4 * tid + 1];
        float a2 = su[4 * tid + 2], a3 = su[4 * tid + 3];
        float c0 = a0, c1 = c0 + a1, c2 = c1 + a2, c3 = c2 + a3;
        red[tid] = c3; __syncthreads();
        for (int off = 1; off < 256; off <<= 1) {
            float v = (tid >= off) ? red[tid - off] : 0.f;
            __syncthreads();
            red[tid] += v; __syncthreads();
        }
        float base = (tid > 0) ? red[tid - 1] : 0.f;
        pus[4 * tid + 1] = base + c0; pus[4 * tid + 2] = base + c1;
        pus[4 * tid + 3] = base + c2; pus[4 * tid + 4] = base + c3;
        if (tid == 0) pus[0] = 0.f;
    }
    __syncthreads();
    {
        float a0 = sv[4 * tid], a1 = sv[4 * tid + 1];
        float a2 = sv[4 * tid + 2], a3 = sv[4 * tid + 3];
        float c0 = a0, c1 = c0 + a1, c2 = c1 + a2, c3 = c2 + a3;
        red[tid] = c3; __syncthreads();
        for (int off = 1; off < 256; off <<= 1) {
            float v = (tid >= off) ? red[tid - off] : 0.f;
            __syncthreads();
            red[tid] += v; __syncthreads();
        }
        float base = (tid > 0) ? red[tid - 1] : 0.f;
        pvs[4 * tid + 1] = base + c0; pvs[4 * tid + 2] = base + c1;
        pvs[4 * tid + 3] = base + c2; pvs[4 * tid + 4] = base + c3;
        if (tid == 0) pvs[0] = 0.f;
    }
    __syncthreads();

    const float ustot = pus[1024];

    // per-row 1/l
    for (int t = tid; t < 1024; t += 256) {
        int s = ss[t];
        float l = sAi[t] * (ustot - pus[s]) + sBi[t] * pvs[s];
        slinv[t] = __fdividef(1.f, l);
    }
    __syncthreads();

    // chunk staging mapping
    const int rl = tid >> 3;            // 0..31 row within chunk
    const int cb = (tid & 7) * 64;      // byte offset within 512B row

    // ---- pass A: Utot (vector, per-thread column) ----
#pragma unroll
    for (int pc = 0; pc < 3; pc++) {
        const char* src = whbB + (size_t)sidx[pc * 32 + rl] * 512 + cb;
        uint32_t dst = sbase + (uint32_t)(pc & 3) * 16384 + rl * 512 + cb;
        CP16(dst, src); CP16(dst + 16, src + 16);
        CP16(dst + 32, src + 32); CP16(dst + 48, src + 48);
        CP_COMMIT();
    }
    float Utot = 0.f;
    for (int c = 0; c < 32; c++) {
        if (c + 3 < 32) {
            const int pc = c + 3;
            const char* src = whbB + (size_t)sidx[pc * 32 + rl] * 512 + cb;
            uint32_t dst = sbase + (uint32_t)(pc & 3) * 16384 + rl * 512 + cb;
            CP16(dst, src); CP16(dst + 16, src + 16);
            CP16(dst + 32, src + 32); CP16(dst + 48, src + 48);
            CP_COMMIT();
        }
        pipe_wait(c);
        __syncthreads();
        const __nv_bfloat16* buf = (const __nv_bfloat16*)(sm + (c & 3) * 16384);
#pragma unroll 8
        for (int q = 0; q < 32; q++) {
            float w = __bfloat162float(buf[q * 256 + tid]);
            Utot = fmaf(su[c * 32 + q], w, Utot);
        }
        __syncthreads();
    }

    // ---- pass B: prefix sweep + inline emission ----
    const int b = bh >> 3, h = bh & 7;
    float prefU = 0.f, prefV = 0.f;
    int ep = 0;

    while (ep < 1024 && ss[ep] == 0) {
        float x = sAi[ep] * Utot * slinv[ep];
        x = fmaxf(x, 0.f);
        float y = __fdividef(1.f, 1.f + __expf(-x));
        out[(size_t)(b * NN + iidx[ep]) * (HH * FOUT) + h * FOUT + tid] = y;
        ep++;
    }

#pragma unroll
    for (int pc = 0; pc < 3; pc++) {
        const char* src = whbB + (size_t)sidx[pc * 32 + rl] * 512 + cb;
        uint32_t dst = sbase + (uint32_t)(pc & 3) * 16384 + rl * 512 + cb;
        CP16(dst, src); CP16(dst + 16, src + 16);
        CP16(dst + 32, src + 32); CP16(dst + 48, src + 48);
        CP_COMMIT();
    }
    for (int c = 0; c < 32; c++) {
        if (c + 3 < 32) {
            const int pc = c + 3;
            const char* src = whbB + (size_t)sidx[pc * 32 + rl] * 512 + cb;
            uint32_t dst = sbase + (uint32_t)(pc & 3) * 16384 + rl * 512 + cb;
            CP16(dst, src); CP16(dst + 16, src + 16);
            CP16(dst + 32, src + 32); CP16(dst + 48, src + 48);
            CP_COMMIT();
        }
        pipe_wait(c);
        __syncthreads();
        const __nv_bfloat16* buf = (const __nv_bfloat16*)(sm + (c & 3) * 16384);
        for (int q = 0; q < 32; q++) {
            const int r = c * 32 + q;
            float w = __bfloat162float(buf[q * 256 + tid]);
            prefU = fmaf(su[r], w, prefU);
            prefV = fmaf(sv[r], w, prefV);
            while (ep < 1024 && ss[ep] == r + 1) {
                float x = (sAi[ep] * (Utot - prefU) + sBi[ep] * prefV) * slinv[ep];
                x = fmaxf(x, 0.f);
                float y = __fdividef(1.f, 1.f + __expf(-x));
                out[(size_t)(b * NN + iidx[ep]) * (HH * FOUT) + h * FOUT + tid] = y;
                ep++;
            }
        }
        __syncthreads();
    }
}

// ---------------------------------------------------------------------------
extern "C" void kernel_launch(void* const* d_in, const int* in_sizes, int n_in,
                              void* d_out, int out_size)
{
    (void)in_sizes; (void)n_in; (void)out_size;
    const float* h_in = (const float*)d_in[0];
    const float* W    = (const float*)d_in[1];
    const float* bW   = (const float*)d_in[2];
    const float* a1   = (const float*)d_in[3];
    const float* a2   = (const float*)d_in[4];
    const float* bA   = (const float*)d_in[5];
    float* out = (float*)d_out;

    split_h_kernel<<<16384, 256>>>(h_in);
    split_w_kernel<<<2048, 256>>>(W);

    cudaFuncSetAttribute(gemm1_cp_kernel,
                         cudaFuncAttributeMaxDynamicSharedMemorySize, G1_SMEM);
    gemm1_cp_kernel<<<dim3(128, 16), 256, G1_SMEM>>>(bW);

    score_kernel<<<(BB * HH * NN) / 8, 256>>>(a1, a2, bA);

    cudaFuncSetAttribute(attn_scan2_kernel,
                         cudaFuncAttributeMaxDynamicSharedMemorySize, ASCAN_SMEM);
    attn_scan2_kernel<<<BB * HH, 256, ASCAN_SMEM>>>(out);
}

// round 14
// speedup vs baseline: 2.5810x; 1.2450x over previous
#include <cuda_runtime.h>
#include <cuda_bf16.h>
#include <stdint.h>
#include <math.h>

#define BB 16
#define NN 1024
#define FIN 256
#define FOUT 256
#define HH 8
#define ALPHA 0.2f

// Scratch (device globals; no allocations allowed)
__device__ float g_Wh[(size_t)BB * HH * NN * FOUT];
__device__ __nv_bfloat16 g_Whb[(size_t)BB * HH * NN * FOUT];
__device__ float g_ei[BB * HH * NN];
__device__ float g_ejb[BB * HH * NN];
__device__ __nv_bfloat16 g_hb[(size_t)8 * 16384 * 32];
__device__ __nv_bfloat16 g_hs[(size_t)8 * 16384 * 32];
__device__ __nv_bfloat16 g_wb[(size_t)8 * 2048 * 32];
__device__ __nv_bfloat16 g_ws[(size_t)8 * 2048 * 32];

#define MMA_BF16(c, a0, a1, a2, a3, b0, b1) \
    asm volatile("mma.sync.aligned.m16n8k16.row.col.f32.bf16.bf16.f32 " \
        "{%0,%1,%2,%3}, {%4,%5,%6,%7}, {%8,%9}, {%0,%1,%2,%3};" \
        : "+f"((c)[0]), "+f"((c)[1]), "+f"((c)[2]), "+f"((c)[3]) \
        : "r"(a0), "r"(a1), "r"(a2), "r"(a3), "r"(b0), "r"(b1))

#define PACK_BF16X2(r, lo, hi) \
    asm("cvt.rn.bf16x2.f32 %0, %1, %2;" : "=r"(r) : "f"(hi), "f"(lo))

#define CP16(dst, src) \
    asm volatile("cp.async.cg.shared.global [%0], [%1], 16;" :: "r"(dst), "l"(src) : "memory")
#define CP_COMMIT() asm volatile("cp.async.commit_group;" ::: "memory")
#define CP_WAIT0()  asm volatile("cp.async.wait_group 0;" ::: "memory")
#define CP_WAIT1()  asm volatile("cp.async.wait_group 1;" ::: "memory")

__device__ __forceinline__ uint32_t smem_u32(const void* p) {
    uint32_t a;
    asm("{ .reg .u64 t; cvta.to.shared.u64 t, %1; cvt.u32.u64 %0, t; }"
        : "=r"(a) : "l"(p));
    return a;
}
__device__ __forceinline__ void ldsm_x4(uint32_t& r0, uint32_t& r1,
                                        uint32_t& r2, uint32_t& r3, uint32_t addr) {
    asm volatile("ldmatrix.sync.aligned.m8n8.x4.shared.b16 {%0,%1,%2,%3}, [%4];"
                 : "=r"(r0), "=r"(r1), "=r"(r2), "=r"(r3) : "r"(addr));
}

// ---------------------------------------------------------------------------
// Prep: split fp32 -> big/small bf16, k-tiled [kt][row][32]
// ---------------------------------------------------------------------------
__global__ void split_h_kernel(const float* __restrict__ src)
{
    const int m = blockIdx.x;
    const int k = threadIdx.x;
    float x = src[(size_t)m * 256 + k];
    __nv_bfloat16 b = __float2bfloat16(x);
    __nv_bfloat16 s = __float2bfloat16(x - __bfloat162float(b));
    size_t idx = ((size_t)(k >> 5) * 16384 + m) * 32 + (k & 31);
    g_hb[idx] = b;
    g_hs[idx] = s;
}
__global__ void split_w_kernel(const float* __restrict__ src)
{
    const int j = blockIdx.x;
    const int k = threadIdx.x;
    float x = src[(size_t)j * 256 + k];
    __nv_bfloat16 b = __float2bfloat16(x);
    __nv_bfloat16 s = __float2bfloat16(x - __bfloat162float(b));
    size_t idx = ((size_t)(k >> 5) * 2048 + j) * 32 + (k & 31);
    g_wb[idx] = b;
    g_ws[idx] = s;
}

// ---------------------------------------------------------------------------
// Kernel 1: Wh = h @ W^T + bW via 3xBF16 m16n8k16 + cp.async (unchanged R8)
// ---------------------------------------------------------------------------
#define G1_PLANE_B 8192
#define G1_BUF (4 * G1_PLANE_B)
#define G1_SMEM (3 * G1_BUF)

__global__ void __launch_bounds__(256, 2) gemm1_cp_kernel(const float* __restrict__ bWp)
{
    extern __shared__ char gsm[];
    const uint32_t sbuf = smem_u32(gsm);

    const int tid  = threadIdx.x;
    const int lane = tid & 31;
    const int wid  = tid >> 5;
    const int mw   = wid & 1;
    const int nw   = wid >> 1;
    const int tg   = lane & 3;
    const int g    = lane >> 2;
    const int m0   = blockIdx.x * 128;
    const int j0   = blockIdx.y * 128;

    const int lrow = tid & 127;
    const int kh   = tid >> 7;
    const int swzr = (lrow & 3) ^ ((lrow >> 2) & 3);
    const uint32_t d0 = (uint32_t)lrow * 64 + (((2 * kh)     ^ swzr) << 4);
    const uint32_t d1 = (uint32_t)lrow * 64 + (((2 * kh + 1) ^ swzr) << 4);
    const char* srcAb = (const char*)g_hb + ((size_t)(m0 + lrow)) * 64 + kh * 32;
    const char* srcAs = (const char*)g_hs + ((size_t)(m0 + lrow)) * 64 + kh * 32;
    const char* srcBb = (const char*)g_wb + ((size_t)(j0 + lrow)) * 64 + kh * 32;
    const char* srcBs = (const char*)g_ws + ((size_t)(j0 + lrow)) * 64 + kh * 32;

    const int lro  = (lane & 7) + ((lane >> 3) & 1) * 8;
    const int lkc  = lane >> 4;
    const int swzL = (lro & 3) ^ ((lro >> 2) & 3);

    float acc[4][4][4];
#pragma unroll
    for (int mi = 0; mi < 4; mi++)
#pragma unroll
        for (int f = 0; f < 4; f++)
#pragma unroll
            for (int c = 0; c < 4; c++) acc[mi][f][c] = 0.f;

    {
        const uint32_t bb = sbuf;
        CP16(bb + d0, srcAb); CP16(bb + d1, srcAb + 16);
        CP16(bb + G1_PLANE_B + d0, srcAs); CP16(bb + G1_PLANE_B + d1, srcAs + 16);
        CP16(bb + 2 * G1_PLANE_B + d0, srcBb); CP16(bb + 2 * G1_PLANE_B + d1, srcBb + 16);
        CP16(bb + 3 * G1_PLANE_B + d0, srcBs); CP16(bb + 3 * G1_PLANE_B + d1, srcBs + 16);
        CP_COMMIT();
    }

    for (int kt = 0; kt < 8; kt++) {
        if (kt < 7) {
            const uint32_t bb = sbuf + ((kt + 1) % 3) * G1_BUF;
            const size_t offA = (size_t)(kt + 1) * (16384 * 64);
            const size_t offB = (size_t)(kt + 1) * (2048 * 64);
            CP16(bb + d0, srcAb + offA); CP16(bb + d1, srcAb + offA + 16);
            CP16(bb + G1_PLANE_B + d0, srcAs + offA); CP16(bb + G1_PLANE_B + d1, srcAs + offA + 16);
            CP16(bb + 2 * G1_PLANE_B + d0, srcBb + offB); CP16(bb + 2 * G1_PLANE_B + d1, srcBb + offB + 16);
            CP16(bb + 3 * G1_PLANE_B + d0, srcBs + offB); CP16(bb + 3 * G1_PLANE_B + d1, srcBs + offB + 16);
            CP_COMMIT();
            CP_WAIT1();
        } else {
            CP_WAIT0();
        }
        __syncthreads();

        const uint32_t base = sbuf + (kt % 3) * G1_BUF;
        const uint32_t sAb = base;
        const uint32_t sAs = base + G1_PLANE_B;
        const uint32_t sBb = base + 2 * G1_PLANE_B;
        const uint32_t sBs = base + 3 * G1_PLANE_B;

#pragma unroll
        for (int ks = 0; ks < 2; ks++) {
            const int kc = 2 * ks + lkc;
            const uint32_t csw = (uint32_t)((kc ^ swzL) << 4);

            uint32_t ab[4][4], as_[4][4];
#pragma unroll
            for (int mi = 0; mi < 4; mi++) {
                uint32_t ro = (uint32_t)(mw * 64 + mi * 16 + lro) * 64 + csw;
                ldsm_x4(ab[mi][0], ab[mi][1], ab[mi][2], ab[mi][3], sAb + ro);
                ldsm_x4(as_[mi][0], as_[mi][1], as_[mi][2], as_[mi][3], sAs + ro);
            }
            uint32_t bbg[2][4], bsm[2][4];
#pragma unroll
            for (int fp = 0; fp < 2; fp++) {
                uint32_t ro = (uint32_t)(nw * 32 + fp * 16 + lro) * 64 + csw;
                ldsm_x4(bbg[fp][0], bbg[fp][1], bbg[fp][2], bbg[fp][3], sBb + ro);
                ldsm_x4(bsm[fp][0], bsm[fp][1], bsm[fp][2], bsm[fp][3], sBs + ro);
            }
#pragma unroll
            for (int fp = 0; fp < 2; fp++) {
#pragma unroll
                for (int sub = 0; sub < 2; sub++) {
                    const int f = fp * 2 + sub;
                    const uint32_t b0g = bbg[fp][sub], b1g = bbg[fp][2 + sub];
                    const uint32_t b0s = bsm[fp][sub], b1s = bsm[fp][2 + sub];
#pragma unroll
                    for (int mi = 0; mi < 4; mi++) {
                        MMA_BF16(acc[mi][f], ab[mi][0], ab[mi][1], ab[mi][2], ab[mi][3], b0g, b1g);
                        MMA_BF16(acc[mi][f], as_[mi][0], as_[mi][1], as_[mi][2], as_[mi][3], b0g, b1g);
                        MMA_BF16(acc[mi][f], ab[mi][0], ab[mi][1], ab[mi][2], ab[mi][3], b0s, b1s);
                    }
                }
            }
        }
    }

#pragma unroll
    for (int f = 0; f < 4; f++) {
        const int c = j0 + nw * 32 + f * 8 + tg * 2;
        const float bw0 = bWp[c];
        const float bw1 = bWp[c + 1];
        const int h = c >> 8;
        const int o = c & 255;
#pragma unroll
        for (int mi = 0; mi < 4; mi++) {
            int r0 = m0 + mw * 64 + mi * 16 + g;
            int b0i = r0 >> 10, n0i = r0 & 1023;
            int r1 = r0 + 8;
            int b1i = r1 >> 10, n1i = r1 & 1023;
            float2 v0, v1;
            v0.x = acc[mi][f][0] + bw0; v0.y = acc[mi][f][1] + bw1;
            v1.x = acc[mi][f][2] + bw0; v1.y = acc[mi][f][3] + bw1;
            size_t i0 = ((size_t)(b0i * HH + h) * NN + n0i) * FOUT + o;
            size_t i1 = ((size_t)(b1i * HH + h) * NN + n1i) * FOUT + o;
            *(float2*)(g_Wh + i0) = v0;
            *(float2*)(g_Wh + i1) = v1;
            uint32_t u0, u1;
            PACK_BF16X2(u0, v0.x, v0.y);
            PACK_BF16X2(u1, v1.x, v1.y);
            *(uint32_t*)((char*)g_Whb + i0 * 2) = u0;
            *(uint32_t*)((char*)g_Whb + i1 * 2) = u1;
        }
    }
}

// ---------------------------------------------------------------------------
// Kernel 2: ei / ejb projections (unchanged)
// ---------------------------------------------------------------------------
__global__ void __launch_bounds__(256) score_kernel(const float* __restrict__ a1,
                                                    const float* __restrict__ a2,
                                                    const float* __restrict__ bA)
{
    const int warp = threadIdx.x >> 5;
    const int lane = threadIdx.x & 31;
    const int row = blockIdx.x * 8 + warp;
    const int h = (row >> 10) & (HH - 1);

    const float4* wr = (const float4*)(g_Wh + (size_t)row * FOUT);
    const float4* p1 = (const float4*)(a1 + h * FOUT);
    const float4* p2 = (const float4*)(a2 + h * FOUT);

    float s1 = 0.f, s2 = 0.f;
#pragma unroll
    for (int u = 0; u < 2; u++) {
        float4 v = wr[lane + u * 32];
        float4 x = p1[lane + u * 32];
        float4 y = p2[lane + u * 32];
        s1 += v.x * x.x + v.y * x.y + v.z * x.z + v.w * x.w;
        s2 += v.x * y.x + v.y * y.y + v.z * y.z + v.w * y.w;
    }
#pragma unroll
    for (int off = 16; off > 0; off >>= 1) {
        s1 += __shfl_xor_sync(0xffffffffu, s1, off);
        s2 += __shfl_xor_sync(0xffffffffu, s2, off);
    }
    if (lane == 0) {
        g_ei[row] = s1;
        g_ejb[row] = s2 + bA[h];
    }
}

// ---------------------------------------------------------------------------
// Kernel 3 (scan v4): 4-way rank-parallel sorted prefix-scan attention.
// 1024 threads = 4 groups x 256 (group g owns ranks [256g, 256g+256)).
// Phase 1: per-group partial sums PU/PV (per column). Phase 2: per-group
// sweep with checkpoint init, emitting rows with split s in (256g, 256g+256].
// smem layout (bytes):
//   [0, 131072)  4 groups x 2 chunk buffers x 16KB
//   tables at 131072+: skey,sidx,ikey,iidx,su,sv,sAi,sBi,ss,slinv (4KB each)
//   pus @172032 (4224), pvs @176256 (4224), red @180480 (4096),
//   PUa @184576 (4096), PVa @188672 (4096)   -> total 192768
// ---------------------------------------------------------------------------
#define ASC_SMEM 192768

__global__ void __launch_bounds__(1024) attn_scan4_kernel(float* __restrict__ out)
{
    extern __shared__ char sm[];
    float* skey  = (float*)(sm + 131072);
    int*   sidx  = (int*)  (sm + 135168);
    float* ikey  = (float*)(sm + 139264);
    int*   iidx  = (int*)  (sm + 143360);
    float* su    = (float*)(sm + 147456);
    float* sv    = (float*)(sm + 151552);
    float* sAi   = (float*)(sm + 155648);
    float* sBi   = (float*)(sm + 159744);
    int*   ss    = (int*)  (sm + 163840);
    float* slinv = (float*)(sm + 167936);
    float* pus   = (float*)(sm + 172032);
    float* pvs   = (float*)(sm + 176256);
    float* red   = (float*)(sm + 180480);
    float* PUa   = (float*)(sm + 184576);
    float* PVa   = (float*)(sm + 188672);
    const uint32_t sbase = smem_u32(sm);

    const int bh  = blockIdx.x;
    const int tid = threadIdx.x;
    const int grp = tid >> 8;
    const int col = tid & 255;
    const char* whbB = (const char*)g_Whb + (size_t)bh * (NN * FOUT) * 2;

    skey[tid] = g_ejb[bh * 1024 + tid];  sidx[tid] = tid;
    ikey[tid] = -g_ei[bh * 1024 + tid];  iidx[tid] = tid;
    __syncthreads();

    // fused dual bitonic sort (ascending), 1 element per thread
    for (int k = 2; k <= 1024; k <<= 1) {
        for (int j = k >> 1; j > 0; j >>= 1) {
            const int t = tid, p = t ^ j;
            if (p > t) {
                bool up = ((t & k) == 0);
                float a = skey[t], bv = skey[p];
                if ((a > bv) == up) {
                    skey[t] = bv; skey[p] = a;
                    int ia = sidx[t]; sidx[t] = sidx[p]; sidx[p] = ia;
                }
                float c = ikey[t], d = ikey[p];
                if ((c > d) == up) {
                    ikey[t] = d; ikey[p] = c;
                    int ib = iidx[t]; iidx[t] = iidx[p]; iidx[p] = ib;
                }
            }
            __syncthreads();
        }
    }

    // per-rank exps + per-row split point
    {
        float e = skey[tid];
        su[tid] = __expf(e);
        sv[tid] = __expf(ALPHA * e);
        float ei = -ikey[tid];
        sAi[tid] = __expf(ei);
        sBi[tid] = __expf(ALPHA * ei);
        float thr = ikey[tid];
        int lo = 0, hi = 1024;
        while (lo < hi) {
            int mid = (lo + hi) >> 1;
            if (skey[mid] <= thr) lo = mid + 1; else hi = mid;
        }
        ss[tid] = lo;
    }
    __syncthreads();

    // scalar exclusive scans su->pus, sv->pvs (1024-thread Hillis-Steele)
    red[tid] = su[tid]; __syncthreads();
    for (int off = 1; off < 1024; off <<= 1) {
        float v = (tid >= off) ? red[tid - off] : 0.f;
        __syncthreads();
        red[tid] += v; __syncthreads();
    }
    pus[tid + 1] = red[tid];
    if (tid == 0) pus[0] = 0.f;
    __syncthreads();

    red[tid] = sv[tid]; __syncthreads();
    for (int off = 1; off < 1024; off <<= 1) {
        float v = (tid >= off) ? red[tid - off] : 0.f;
        __syncthreads();
        red[tid] += v; __syncthreads();
    }
    pvs[tid + 1] = red[tid];
    if (tid == 0) pvs[0] = 0.f;
    __syncthreads();

    const float ustot = pus[1024];

    // per-row 1/l
    {
        int s = ss[tid];
        float l = sAi[tid] * (ustot - pus[s]) + sBi[tid] * pvs[s];
        slinv[tid] = __fdividef(1.f, l);
    }
    __syncthreads();

    // chunk staging mapping (within group)
    const int rbase = grp * 256;
    const int rl = col >> 3;
    const int cb = (col & 7) * 64;
    const uint32_t gbuf = sbase + (uint32_t)grp * 32768;

    // ---- Phase 1: per-group partial sums PU/PV over 256 ranks ----
    {
        const char* src = whbB + (size_t)sidx[rbase + rl] * 512 + cb;
        uint32_t dst = gbuf + rl * 512 + cb;
        CP16(dst, src); CP16(dst + 16, src + 16);
        CP16(dst + 32, src + 32); CP16(dst + 48, src + 48);
        CP_COMMIT();
    }
    float pU = 0.f, pV = 0.f;
    for (int c = 0; c < 8; c++) {
        if (c < 7) {
            const char* src = whbB + (size_t)sidx[rbase + (c + 1) * 32 + rl] * 512 + cb;
            uint32_t dst = gbuf + (uint32_t)((c + 1) & 1) * 16384 + rl * 512 + cb;
            CP16(dst, src); CP16(dst + 16, src + 16);
            CP16(dst + 32, src + 32); CP16(dst + 48, src + 48);
            CP_COMMIT();
            CP_WAIT1();
        } else {
            CP_WAIT0();
        }
        __syncthreads();
        const __nv_bfloat16* buf = (const __nv_bfloat16*)(sm + grp * 32768 + (c & 1) * 16384);
#pragma unroll 8
        for (int q = 0; q < 32; q++) {
            const int r = rbase + c * 32 + q;
            float w = __bfloat162float(buf[q * 256 + col]);
            pU = fmaf(su[r], w, pU);
            pV = fmaf(sv[r], w, pV);
        }
        __syncthreads();
    }
    PUa[grp * 256 + col] = pU;
    PVa[grp * 256 + col] = pV;
    __syncthreads();

    // prefix init + Utot (per column)
    float prefU = 0.f, prefV = 0.f, Utot = 0.f;
#pragma unroll
    for (int k = 0; k < 4; k++) {
        float u = PUa[k * 256 + col];
        float v = PVa[k * 256 + col];
        Utot += u;
        if (k < grp) { prefU += u; prefV += v; }
    }

    // emission start: first row with ss >= rbase+1
    int ep;
    {
        int lo = 0, hi = 1024, target = rbase + 1;
        while (lo < hi) {
            int mid = (lo + hi) >> 1;
            if (ss[mid] < target) lo = mid + 1; else hi = mid;
        }
        ep = lo;
    }
    const int b = bh >> 3, h = bh & 7;

    // group 0 pre-emits rows with s == 0
    if (grp == 0) {
        int e0 = 0;
        while (e0 < 1024 && ss[e0] == 0) {
            float x = sAi[e0] * Utot * slinv[e0];
            x = fmaxf(x, 0.f);
            float y = __fdividef(1.f, 1.f + __expf(-x));
            out[(size_t)(b * NN + iidx[e0]) * (HH * FOUT) + h * FOUT + col] = y;
            e0++;
        }
    }

    // ---- Phase 2: per-group sweep + inline emission ----
    const int rend = rbase + 256;
    {
        const char* src = whbB + (size_t)sidx[rbase + rl] * 512 + cb;
        uint32_t dst = gbuf + rl * 512 + cb;
        CP16(dst, src); CP16(dst + 16, src + 16);
        CP16(dst + 32, src + 32); CP16(dst + 48, src + 48);
        CP_COMMIT();
    }
    for (int c = 0; c < 8; c++) {
        if (c < 7) {
            const char* src = whbB + (size_t)sidx[rbase + (c + 1) * 32 + rl] * 512 + cb;
            uint32_t dst = gbuf + (uint32_t)((c + 1) & 1) * 16384 + rl * 512 + cb;
            CP16(dst, src); CP16(dst + 16, src + 16);
            CP16(dst + 32, src + 32); CP16(dst + 48, src + 48);
            CP_COMMIT();
            CP_WAIT1();
        } else {
            CP_WAIT0();
        }
        __syncthreads();
        const __nv_bfloat16* buf = (const __nv_bfloat16*)(sm + grp * 32768 + (c & 1) * 16384);
        for (int q = 0; q < 32; q++) {
            const int r = rbase + c * 32 + q;
            float w = __bfloat162float(buf[q * 256 + col]);
            prefU = fmaf(su[r], w, prefU);
            prefV = fmaf(sv[r], w, prefV);
            while (ep < 1024 && ss[ep] == r + 1) {
                float x = (sAi[ep] * (Utot - prefU) + sBi[ep] * prefV) * slinv[ep];
                x = fmaxf(x, 0.f);
                float y = __fdividef(1.f, 1.f + __expf(-x));
                out[(size_t)(b * NN + iidx[ep]) * (HH * FOUT) + h * FOUT + col] = y;
                ep++;
            }
        }
        __syncthreads();
    }
    (void)rend;
}

// ---------------------------------------------------------------------------
extern "C" void kernel_launch(void* const* d_in, const int* in_sizes, int n_in,
                              void* d_out, int out_size)
{
    (void)in_sizes; (void)n_in; (void)out_size;
    const float* h_in = (const float*)d_in[0];
    const float* W    = (const float*)d_in[1];
    const float* bW   = (const float*)d_in[2];
    const float* a1   = (const float*)d_in[3];
    const float* a2   = (const float*)d_in[4];
    const float* bA   = (const float*)d_in[5];
    float* out = (float*)d_out;

    split_h_kernel<<<16384, 256>>>(h_in);
    split_w_kernel<<<2048, 256>>>(W);

    cudaFuncSetAttribute(gemm1_cp_kernel,
                         cudaFuncAttributeMaxDynamicSharedMemorySize, G1_SMEM);
    gemm1_cp_kernel<<<dim3(128, 16), 256, G1_SMEM>>>(bW);

    score_kernel<<<(BB * HH * NN) / 8, 256>>>(a1, a2, bA);

    cudaFuncSetAttribute(attn_scan4_kernel,
                         cudaFuncAttributeMaxDynamicSharedMemorySize, ASC_SMEM);
    attn_scan4_kernel<<<BB * HH, 1024, ASC_SMEM>>>(out);
}